// round 17
// baseline (speedup 1.0000x reference)
#include <cuda_runtime.h>
#include <math.h>

#define BB 16
#define NN 4096
#define DD 64
#define KK 8
#define HH 4
#define EPSF 1e-5f
// 16 * (-0.5 * 64 * ln(2*pi))
#define LOGPI_SUM (-940.99305800158484f)

typedef unsigned long long ull;

// ---------------- packed f32x2 helpers --------------------------------------
__device__ __forceinline__ ull pk2(float x, float y) {
    ull r; asm("mov.b64 %0, {%1, %2};" : "=l"(r) : "f"(x), "f"(y)); return r;
}
__device__ __forceinline__ void fma2(ull& d, ull a, ull b) {
    asm("fma.rn.f32x2 %0, %1, %2, %0;" : "+l"(d) : "l"(a), "l"(b));
}
__device__ __forceinline__ ull fma2r(ull a, ull b, ull c) {
    ull d; asm("fma.rn.f32x2 %0, %1, %2, %3;" : "=l"(d) : "l"(a), "l"(b), "l"(c)); return d;
}
__device__ __forceinline__ ull mul2(ull a, ull b) {
    ull d; asm("mul.rn.f32x2 %0, %1, %2;" : "=l"(d) : "l"(a), "l"(b)); return d;
}
union F4U { float4 v; ull u[2]; float s[4]; };

// ---------------- scratch (static device memory) ---------------------------
__device__ float g_x[BB * NN * DD];
__device__ float g_keys[(size_t)BB * NN * KK * DD];    // [b][n][k][d]
__device__ float g_slots[BB * KK * DD];
__device__ float g_sigma[BB * KK * DD];
__device__ float g_a[BB * KK * DD];     // -0.5/(sigma^2+eps)
__device__ float g_bq[BB * KK * DD];    // q/(sigma^2+eps)
__device__ float g_C[BB * KK * HH];     // logit bias per (b,k,h)
__device__ float g_A[BB * KK * HH];     // sum attn
__device__ float g_S2[BB * KK * DD];    // sum attn*k^2
__device__ float g_T[BB * KK * HH * DD];// sum attn*x  [b][k][h][e]
__device__ unsigned g_cnt[3 * BB];      // per-(iter,batch) completion counters
// pre-transposed weights
__device__ float g_wT[2 * 64 * 192];    // [s][e*192+row], row = gate*64+d
__device__ float g_w1T[64 * 256];       // [e*256+j]
__device__ float g_w2T[256 * 64];       // [j*64+d]

// ---------------- fused LN + keys GEMM + slot init + weight transpose -------
// blocks [0,512): LN + keys.  [512,640): init.  [640,752): weight transpose.
__global__ __launch_bounds__(128, 4) void k_lnkeys(
        const float* __restrict__ emb, const float* __restrict__ lng,
        const float* __restrict__ lnb, const float* __restrict__ tk,
        const float* __restrict__ mu, const float* __restrict__ ls,
        const float* __restrict__ mix0, const float* __restrict__ noise,
        const float* __restrict__ tq, const float* __restrict__ gsl,
        const float* __restrict__ bsl,
        const float* __restrict__ wih, const float* __restrict__ whh,
        const float* __restrict__ w1, const float* __restrict__ w2) {
    __shared__ float xs[64 * 128];   // [e][n]  32 KB (transposed)
    __shared__ float ws[64 * 64];    // [e][d]  16 KB
    int t = threadIdx.x;

    if (blockIdx.x >= BB * 32 + BB * KK) {
        // ---------------- weight transpose path ------------------------------
#pragma unroll
        for (int i = 0; i < 4; i++) {
            int id = (blockIdx.x - (BB * 32 + BB * KK)) * 512 + i * 128 + t;
            if (id < 24576) {
                int s = id >= 12288;
                int loc = id - s * 12288;
                int row = loc >> 6, e = loc & 63;
                g_wT[s * 12288 + e * 192 + row] = (s ? whh : wih)[loc];
            } else if (id < 40960) {
                int loc = id - 24576;
                int j = loc >> 6, e = loc & 63;
                g_w1T[e * 256 + j] = w1[loc];
            } else {
                int loc = id - 40960;
                int dd2 = loc >> 8, j = loc & 255;
                g_w2T[j * 64 + dd2] = w2[loc];
            }
        }
        return;
    }
    if (blockIdx.x >= BB * 32) {
        // ---------------- init path ------------------------------------------
        int bk = blockIdx.x - BB * 32;
        int k = bk & (KK - 1);
        if (bk == 0 && t < 3 * BB) g_cnt[t] = 0u;
        float* sh2 = ws;
        float sg = 0.f, slot = 0.f;
        if (t < 64) {
            sg = expf(ls[k * 64 + t]);
            slot = mu[k * 64 + t] + sg * noise[bk * 64 + t];
            g_sigma[bk * 64 + t] = sg;
            g_slots[bk * 64 + t] = slot;
            sh2[t] = slot;
        }
        __syncthreads();
        if (t < 64) {
            int d = t, h = d >> 4;
            float m = 0.f, q = 0.f;
#pragma unroll
            for (int j = 0; j < 64; j++) { float v = sh2[j]; m += v; q += v * v; }
            m *= (1.f / 64.f);
            float var = q * (1.f / 64.f) - m * m;
            float sln = (slot - m) * rsqrtf(var + EPSF) * gsl[d] + bsl[d];
            float qd = sln * tq[((size_t)k * 64 + d) * 64 + d];
            float invden = 1.f / (sg * sg + EPSF);
            g_a[bk * 64 + d] = -0.5f * invden;
            g_bq[bk * 64 + d] = qd * invden;
            float cp = -logf(fmaxf(sg, EPSF)) - 0.5f * qd * qd * invden;
#pragma unroll
            for (int o = 1; o < 16; o <<= 1) cp += __shfl_xor_sync(0xffffffffu, cp, o);
            if ((d & 15) == 0) g_C[bk * 4 + h] = logf(mix0[k] + EPSF) + LOGPI_SUM + cp;
            g_S2[bk * 64 + d] = 0.f;
            if (d < 4) g_A[bk * 4 + d] = 0.f;
#pragma unroll
            for (int i = 0; i < 4; i++) g_T[bk * 256 + i * 64 + d] = 0.f;
        }
        return;
    }

    // ---------------- LN + keys path -----------------------------------------
    int b = blockIdx.x >> 5;
    int n0 = (blockIdx.x & 31) << 7;
    {
        const float4* xg = (const float4*)(emb + ((size_t)b * NN + n0) * 64);
#pragma unroll
        for (int r = 0; r < 16; r++) {
            int idx = t + r * 128;
            int n = idx & 127, e4 = idx >> 7;
            float4 v = xg[n * 16 + e4];
            int e0 = e4 << 2;
            xs[(e0 + 0) * 128 + n] = v.x;
            xs[(e0 + 1) * 128 + n] = v.y;
            xs[(e0 + 2) * 128 + n] = v.z;
            xs[(e0 + 3) * 128 + n] = v.w;
        }
    }
    __syncthreads();
    {
        float s = 0.f, q = 0.f;
#pragma unroll 8
        for (int e = 0; e < 64; e++) { float v = xs[e * 128 + t]; s += v; q += v * v; }
        float m = s * (1.f / 64.f);
        float var = q * (1.f / 64.f) - m * m;
        float rr = rsqrtf(var + EPSF);
        float* gx = g_x + ((size_t)b * NN + n0 + t) * 64;
#pragma unroll 4
        for (int e = 0; e < 64; e += 4) {
            float4 o;
            o.x = (xs[(e + 0) * 128 + t] - m) * rr * lng[e + 0] + lnb[e + 0];
            o.y = (xs[(e + 1) * 128 + t] - m) * rr * lng[e + 1] + lnb[e + 1];
            o.z = (xs[(e + 2) * 128 + t] - m) * rr * lng[e + 2] + lnb[e + 2];
            o.w = (xs[(e + 3) * 128 + t] - m) * rr * lng[e + 3] + lnb[e + 3];
            xs[(e + 0) * 128 + t] = o.x;
            xs[(e + 1) * 128 + t] = o.y;
            xs[(e + 2) * 128 + t] = o.z;
            xs[(e + 3) * 128 + t] = o.w;
            *(float4*)&gx[e] = o;
        }
    }
    int tx = t & 7, ty = t >> 3;
    int d0 = tx << 3;     // 0..56
    int nr = ty << 3;     // 0..120
    for (int k = 0; k < KK; k++) {
        __syncthreads();
        const float4* wg = (const float4*)(tk + (size_t)k * 4096);
#pragma unroll
        for (int r = 0; r < 8; r++)
            ((float4*)ws)[t + r * 128] = wg[t + r * 128];
        __syncthreads();
        ull acc[8][4];
#pragma unroll
        for (int n = 0; n < 8; n++)
#pragma unroll
            for (int p = 0; p < 4; p++) acc[n][p] = 0ull;
#pragma unroll 8
        for (int e = 0; e < 64; e++) {
            F4U wa; wa.v = *(const float4*)&ws[e * 64 + d0];
            F4U wb; wb.v = *(const float4*)&ws[e * 64 + d0 + 4];
            F4U xa; xa.v = *(const float4*)&xs[e * 128 + nr];
            F4U xb; xb.v = *(const float4*)&xs[e * 128 + nr + 4];
#pragma unroll
            for (int n = 0; n < 8; n++) {
                float xv = (n < 4) ? xa.s[n] : xb.s[n - 4];
                ull x2 = pk2(xv, xv);
                fma2(acc[n][0], x2, wa.u[0]);
                fma2(acc[n][1], x2, wa.u[1]);
                fma2(acc[n][2], x2, wb.u[0]);
                fma2(acc[n][3], x2, wb.u[1]);
            }
        }
        size_t o0 = (((size_t)b * NN + n0 + nr) * KK + k) * 64 + d0;
#pragma unroll
        for (int n = 0; n < 8; n++) {
            F4U oa, ob;
            oa.u[0] = acc[n][0]; oa.u[1] = acc[n][1];
            ob.u[0] = acc[n][2]; ob.u[1] = acc[n][3];
            *(float4*)&g_keys[o0 + (size_t)n * 512]     = oa.v;
            *(float4*)&g_keys[o0 + (size_t)n * 512 + 4] = ob.v;
        }
    }
}

// ---------------- fused attention pass + tail slot update -------------------
__global__ __launch_bounds__(256, 2) void k_pass(
        float* __restrict__ attn_out, int last, int rev, int it,
        const float* __restrict__ tkm, const float* __restrict__ tvm,
        const float* __restrict__ bih, const float* __restrict__ bhh,
        const float* __restrict__ b1, const float* __restrict__ b2,
        const float* __restrict__ gff, const float* __restrict__ bff,
        const float* __restrict__ tq, const float* __restrict__ gsl,
        const float* __restrict__ bsl,
        const float* __restrict__ noisef, float* __restrict__ out_slots) {
    __shared__ float4 xs[2048];       // [n][e/4]  32 KB
    __shared__ float attn_s[4096];    // [n][kh]   16 KB
    __shared__ int s_lastb;
    int bidx = rev ? ((int)gridDim.x - 1 - (int)blockIdx.x) : (int)blockIdx.x;
    int b = bidx >> 5;
    int n0 = (bidx & 31) << 7;
    int t = threadIdx.x, w = t >> 5, lane = t & 31;
    int bk = b * KK + (lane >> 2);
    int h = lane & 3;
    F4U a4[4], b4[4];
#pragma unroll
    for (int i = 0; i < 4; i++) {
        a4[i].v = *(const float4*)&g_a[bk * 64 + h * 16 + i * 4];
        b4[i].v = *(const float4*)&g_bq[bk * 64 + h * 16 + i * 4];
    }
    float C = g_C[bk * 4 + h];
    for (int i = t; i < 2048; i += 256)
        xs[i] = ((const float4*)g_x)[((size_t)b * NN + n0) * 16 + i];
    __syncthreads();

    F4U S2a[4];
#pragma unroll
    for (int j = 0; j < 4; j++) { S2a[j].u[0] = 0ull; S2a[j].u[1] = 0ull; }
    float Aacc = 0.f;
    float* aout = attn_out + (size_t)bk * NN * 4 + h;
    const float4* kbase = ((const float4*)g_keys) + ((size_t)b * NN + n0) * 128 + lane * 4;

    F4U q0, q1, q2, q3;
    { const float4* kp = kbase + (size_t)(w * 16) * 128;
      q0.v = kp[0]; q1.v = kp[1]; q2.v = kp[2]; q3.v = kp[3]; }
#pragma unroll 2
    for (int ni = 0; ni < 16; ni++) {
        int nl = w * 16 + ni;
        ull kp8[8] = {q0.u[0], q0.u[1], q1.u[0], q1.u[1], q2.u[0], q2.u[1], q3.u[0], q3.u[1]};
        if (ni < 15) {
            const float4* kp = kbase + (size_t)(nl + 1) * 128;
            q0.v = kp[0]; q1.v = kp[1]; q2.v = kp[2]; q3.v = kp[3];
        }
        ull lgp = 0ull;
#pragma unroll
        for (int j = 0; j < 8; j++) {
            ull tmp = fma2r(kp8[j], a4[j >> 1].u[j & 1], b4[j >> 1].u[j & 1]);
            lgp = fma2r(kp8[j], tmp, lgp);
        }
        F4U lgu; lgu.u[0] = lgp;
        float lg = C + lgu.s[0] + lgu.s[1];
        float mm = lg;
        mm = fmaxf(mm, __shfl_xor_sync(0xffffffffu, mm, 4));
        mm = fmaxf(mm, __shfl_xor_sync(0xffffffffu, mm, 8));
        mm = fmaxf(mm, __shfl_xor_sync(0xffffffffu, mm, 16));
        float ex = __expf(lg - mm);
        float ss = ex;
        ss += __shfl_xor_sync(0xffffffffu, ss, 4);
        ss += __shfl_xor_sync(0xffffffffu, ss, 8);
        ss += __shfl_xor_sync(0xffffffffu, ss, 16);
        float attn = __fdividef(ex, ss) + EPSF;
        attn_s[nl * 32 + lane] = attn;
        if (last) aout[(size_t)(n0 + nl) * 4] = attn;
        Aacc += attn;
        ull attn2 = pk2(attn, attn);
#pragma unroll
        for (int j = 0; j < 8; j++) {
            ull ak = mul2(attn2, kp8[j]);
            S2a[j >> 1].u[j & 1] = fma2r(ak, kp8[j], S2a[j >> 1].u[j & 1]);
        }
    }
    __syncthreads();

    // ---- phase 2: T ----
    {
        int kh = t >> 3, et = t & 7;
        ull Tl[4] = {0ull, 0ull, 0ull, 0ull};
        const float* ap = attn_s + kh;
        const float4* xp = xs + et * 2;
#pragma unroll 4
        for (int n = 0; n < 128; n++) {
            float at = ap[n * 32];
            ull at2 = pk2(at, at);
            F4U xa; xa.v = xp[n * 16];
            F4U xb; xb.v = xp[n * 16 + 1];
            Tl[0] = fma2r(at2, xa.u[0], Tl[0]);
            Tl[1] = fma2r(at2, xa.u[1], Tl[1]);
            Tl[2] = fma2r(at2, xb.u[0], Tl[2]);
            Tl[3] = fma2r(at2, xb.u[1], Tl[3]);
        }
        int k2 = kh >> 2, h2 = kh & 3;
        float* gp = &g_T[(size_t)(b * KK + k2) * 256 + h2 * 64 + et * 8];
        F4U o0, o1;
        o0.u[0] = Tl[0]; o0.u[1] = Tl[1];
        o1.u[0] = Tl[2]; o1.u[1] = Tl[3];
#pragma unroll
        for (int j = 0; j < 4; j++) atomicAdd(gp + j, o0.s[j]);
#pragma unroll
        for (int j = 0; j < 4; j++) atomicAdd(gp + 4 + j, o1.s[j]);
    }

    // ---- S2 + A tree ----
    __syncthreads();
    float* redf = attn_s;
#define SIDX(ww, j) ((ww) * 544 + lane * 17 + (j))
    if (w >= 4) {
#pragma unroll
        for (int j = 0; j < 16; j++) redf[SIDX(w - 4, j)] = S2a[j >> 2].s[j & 3];
        redf[SIDX(w - 4, 16)] = Aacc;
    }
    __syncthreads();
    if (w < 4) {
#pragma unroll
        for (int j = 0; j < 16; j++) S2a[j >> 2].s[j & 3] += redf[SIDX(w, j)];
        Aacc += redf[SIDX(w, 16)];
    }
    __syncthreads();
    if (w == 2 || w == 3) {
#pragma unroll
        for (int j = 0; j < 16; j++) redf[SIDX(w - 2, j)] = S2a[j >> 2].s[j & 3];
        redf[SIDX(w - 2, 16)] = Aacc;
    }
    __syncthreads();
    if (w < 2) {
#pragma unroll
        for (int j = 0; j < 16; j++) S2a[j >> 2].s[j & 3] += redf[SIDX(w, j)];
        Aacc += redf[SIDX(w, 16)];
    }
    __syncthreads();
    if (w == 1) {
#pragma unroll
        for (int j = 0; j < 16; j++) redf[SIDX(0, j)] = S2a[j >> 2].s[j & 3];
        redf[SIDX(0, 16)] = Aacc;
    }
    __syncthreads();
    if (w == 0) {
#pragma unroll
        for (int j = 0; j < 16; j++)
            atomicAdd(&g_S2[(size_t)b * 512 + lane * 16 + j],
                      S2a[j >> 2].s[j & 3] + redf[SIDX(0, j)]);
        atomicAdd(&g_A[b * 32 + lane], Aacc + redf[SIDX(0, 16)]);
    }

    // ---- completion counter: last block of batch b runs the slot update ----
    __threadfence();
    __syncthreads();
    if (t == 0) s_lastb = (atomicAdd(&g_cnt[it * BB + b], 1u) == 31u);
    __syncthreads();
    if (!s_lastb) return;

    // scratch overlays (pass smem now free)
    float* Tsh  = attn_s;           // 2048: [k][h*64+e]
    float* S2sh = attn_s + 2048;    // 512
    float* Ash  = attn_s + 2560;    // 32
    float* ush  = attn_s + 2592;    // 512
    float* hshl = attn_s + 3104;    // 512
    float* xsf  = (float*)xs;
    float* gshl  = xsf;             // 3072: [k][g*64+d]
    float* presh = xsf + 3072;      // 512
    float* h1shl = xsf + 3584;      // 2048
    float* shl   = xsf + 5632;      // 512
    float* oshl  = xsf + 6144;      // 512
    float* sgl   = xsf + 6656;      // 512
    for (int i = t; i < 2048; i += 256) Tsh[i] = g_T[(size_t)b * 2048 + i];
    for (int i = t; i < 512; i += 256) { S2sh[i] = g_S2[(size_t)b * 512 + i];
                                         hshl[i] = g_slots[b * 512 + i]; }
    if (t < 32) Ash[t] = g_A[b * 32 + t];
    __syncthreads();
    // phase A: u, s1, sigma (512 items)
#pragma unroll
    for (int r = 0; r < 2; r++) {
        int idx = t + r * 256;
        int kk = idx >> 6, d2 = idx & 63, h2 = (idx >> 4) & 3;
        float Nk = Ash[kk * 4] + Ash[kk * 4 + 1] + Ash[kk * 4 + 2] + Ash[kk * 4 + 3];
        float u = 0.f, s1 = 0.f;
        const float* Trow = Tsh + kk * 256 + h2 * 64;
#pragma unroll 8
        for (int e = 0; e < 64; e++) {
            float tvv = Trow[e];
            u  = fmaf(tvv, tvm[((size_t)kk * 64 + e) * 64 + d2], u);
            s1 = fmaf(tvv, tkm[((size_t)kk * 64 + e) * 64 + d2], s1);
        }
        float invNk = 1.f / Nk;
        u *= (invNk + EPSF);
        float sig2 = fmaxf(S2sh[idx] - 2.f * u * s1 + u * u * Ash[kk * 4 + h2], 0.f);
        float sg = sqrtf(sig2 * invNk) + EPSF;
        g_sigma[b * 512 + idx] = sg;
        sgl[idx] = sg;
        ush[idx] = u;
    }
    __syncthreads();
    // phase B: gates (3072 dots, coalesced via g_wT)
#pragma unroll
    for (int r = 0; r < 12; r++) {
        int idx = t + r * 256;
        int kk = idx / 384, rem = idx - kk * 384;
        int g = rem >> 6, d2 = rem & 63;
        const float* vi = (g < 3) ? (ush + kk * 64) : (hshl + kk * 64);
        const float* W = g_wT + (g < 3 ? 0 : 12288) + (g % 3) * 64 + d2;
        float acc = (g < 3 ? bih : bhh)[(g % 3) * 64 + d2];
#pragma unroll 8
        for (int e = 0; e < 64; e++) acc = fmaf(vi[e], W[e * 192], acc);
        gshl[idx] = acc;
    }
    __syncthreads();
    // phase C: GRU combine + FF LayerNorm
#pragma unroll
    for (int r = 0; r < 2; r++) {
        int idx = t + r * 256;
        int kk = idx >> 6, d2 = idx & 63;
        const float* gk = gshl + kk * 384;
        float rr = 1.f / (1.f + expf(-(gk[d2] + gk[192 + d2])));
        float z = 1.f / (1.f + expf(-(gk[64 + d2] + gk[256 + d2])));
        float nn2 = tanhf(gk[128 + d2] + rr * gk[320 + d2]);
        shl[idx] = (1.f - z) * nn2 + z * hshl[idx];
    }
    __syncthreads();
#pragma unroll
    for (int r = 0; r < 2; r++) {
        int idx = t + r * 256;
        int kk = idx >> 6, d2 = idx & 63;
        const float* row = shl + kk * 64;
        float m = 0.f, qq = 0.f;
#pragma unroll
        for (int j = 0; j < 64; j++) { float v = row[j]; m += v; qq += v * v; }
        m *= (1.f / 64.f);
        float var = qq * (1.f / 64.f) - m * m;
        presh[idx] = (row[d2] - m) * rsqrtf(var + EPSF) * gff[d2] + bff[d2];
    }
    __syncthreads();
    // phase D: h1 (2048 dots)
#pragma unroll
    for (int r = 0; r < 8; r++) {
        int idx = t + r * 256;
        int kk = idx >> 8, j = idx & 255;
        float acc = b1[j];
        const float* wr = g_w1T + j;
        const float* pr = presh + kk * 64;
#pragma unroll 8
        for (int e = 0; e < 64; e++) acc = fmaf(pr[e], wr[e * 256], acc);
        h1shl[idx] = fmaxf(acc, 0.f);
    }
    __syncthreads();
    // phase E: w2 + output
#pragma unroll
    for (int r = 0; r < 2; r++) {
        int idx = t + r * 256;
        int kk = idx >> 6, d2 = idx & 63;
        float o = shl[idx] + b2[d2];
        const float* wr = g_w2T + d2;
        const float* hh = h1shl + kk * 256;
#pragma unroll 8
        for (int j = 0; j < 256; j++) o = fmaf(hh[j], wr[j * 64], o);
        g_slots[b * 512 + idx] = o;
        if (last) out_slots[b * 512 + idx] = o + sgl[idx] * noisef[b * 512 + idx];
        oshl[idx] = o;
    }
    __syncthreads();
    if (!last) {
#pragma unroll
        for (int r = 0; r < 2; r++) {
            int idx = t + r * 256;
            int kk = idx >> 6, d2 = idx & 63, h2 = (idx >> 4) & 3;
            const float* row = oshl + kk * 64;
            float m = 0.f, qq = 0.f;
#pragma unroll
            for (int j = 0; j < 64; j++) { float v = row[j]; m += v; qq += v * v; }
            m *= (1.f / 64.f);
            float var = qq * (1.f / 64.f) - m * m;
            float sln = (row[d2] - m) * rsqrtf(var + EPSF) * gsl[d2] + bsl[d2];
            float qd = sln * tq[((size_t)kk * 64 + d2) * 64 + d2];
            float sg = sgl[idx];
            float invden = 1.f / (sg * sg + EPSF);
            g_a[b * 512 + idx]  = -0.5f * invden;
            g_bq[b * 512 + idx] = qd * invden;
            float cp = -logf(fmaxf(sg, EPSF)) - 0.5f * qd * qd * invden;
#pragma unroll
            for (int o2 = 1; o2 < 16; o2 <<= 1) cp += __shfl_xor_sync(0xffffffffu, cp, o2);
            float Nk = Ash[kk * 4] + Ash[kk * 4 + 1] + Ash[kk * 4 + 2] + Ash[kk * 4 + 3];
            if ((d2 & 15) == 0)
                g_C[(b * KK + kk) * 4 + h2] = logf(Nk * (1.f / (float)NN) + EPSF) + LOGPI_SUM + cp;
            g_S2[b * 512 + idx] = 0.f;
        }
        if (t < 32) g_A[b * 32 + t] = 0.f;
        for (int i = t; i < 2048; i += 256) g_T[(size_t)b * 2048 + i] = 0.f;
    }
}

// ---------------- launch ----------------------------------------------------
extern "C" void kernel_launch(void* const* d_in, const int* in_sizes, int n_in,
                              void* d_out, int out_size) {
    const float* emb   = (const float*)d_in[0];
    const float* mu    = (const float*)d_in[1];
    const float* ls    = (const float*)d_in[2];
    const float* mix0  = (const float*)d_in[3];
    const float* tk    = (const float*)d_in[4];
    const float* tq    = (const float*)d_in[5];
    const float* tv    = (const float*)d_in[6];
    const float* wih   = (const float*)d_in[7];
    const float* whh   = (const float*)d_in[8];
    const float* bih   = (const float*)d_in[9];
    const float* bhh   = (const float*)d_in[10];
    const float* w1    = (const float*)d_in[11];
    const float* b1    = (const float*)d_in[12];
    const float* w2    = (const float*)d_in[13];
    const float* b2    = (const float*)d_in[14];
    const float* ling  = (const float*)d_in[15];
    const float* linb  = (const float*)d_in[16];
    const float* lslg  = (const float*)d_in[17];
    const float* lslb  = (const float*)d_in[18];
    const float* lffg  = (const float*)d_in[19];
    const float* lffb  = (const float*)d_in[20];
    const float* nzi   = (const float*)d_in[21];
    const float* nzf   = (const float*)d_in[22];

    float* out_slots = (float*)d_out;                  // [B,K,D]
    float* out_attn  = (float*)d_out + BB * KK * DD;   // [B,K,N,H]

    k_lnkeys<<<BB * 32 + BB * KK + 112, 128>>>(emb, ling, linb, tk,
                                               mu, ls, mix0, nzi, tq, lslg, lslb,
                                               wih, whh, w1, w2);
    for (int it = 0; it < 3; it++) {
        int last = (it == 2);
        int rev = (it == 1);
        k_pass<<<BB * 32, 256>>>(out_attn, last, rev, it,
                                 tk, tv, bih, bhh, b1, b2, lffg, lffb,
                                 tq, lslg, lslb, nzf, out_slots);
    }
}